// round 1
// baseline (speedup 1.0000x reference)
#include <cuda_runtime.h>

// Net_90434831385322: z = LIM_A + span*sigmoid( relu( ((x-LIM_A)/span) @ W1 + b1 ) @ W2 + b2 )
// Strategy: fold input scaling into W1/b1; per-thread row processing with
// fma.rn.f32x2 packed fp32 FMAs; weights pre-packed in shared memory as pairs.

union F2U { float2 f; unsigned long long u; };

__device__ __forceinline__ float2 ffma2(float2 a, float2 b, float2 c) {
    F2U A, B, C, D;
    A.f = a; B.f = b; C.f = c;
    asm("fma.rn.f32x2 %0, %1, %2, %3;"
        : "=l"(D.u) : "l"(A.u), "l"(B.u), "l"(C.u));
    return D.f;
}

#define HID 64
#define NPAIR 32   // HID/2

__global__ void __launch_bounds__(256)
mlp_kernel(const float4* __restrict__ x,
           const float* __restrict__ W1,   // [4][64] row-major
           const float* __restrict__ b1,   // [64]
           const float* __restrict__ W2,   // [64][4] row-major
           const float* __restrict__ b2,   // [4]
           float4* __restrict__ out,
           int rows)
{
    // Packed shared layouts:
    //  sW1[p*8 + i*2 + s] = W1[i][2p+s] / span[i]      (p=0..31, i=0..3, s=0..1)
    //  sB1[j]             = b1[j] - sum_i lim_a[i]*W1[i][j]/span[i]
    //  sW2[k*64 + j]      = W2[j][k]
    __shared__ float sW1[256];
    __shared__ float sB1[64];
    __shared__ float sW2[256];
    __shared__ float sB2[4];

    const int t = threadIdx.x;

    if (t < 64) {
        const float lim_a[4]    = {0.001f, 0.02f, 0.05f, 0.001f};
        const float inv_span[4] = {1.0f/0.003f, 1.0f/0.03f, 1.0f/0.15f, 1.0f/0.003f};
        const int j = t;
        float wf[4];
        float bf = b1[j];
        #pragma unroll
        for (int i = 0; i < 4; i++) {
            wf[i] = W1[i * HID + j] * inv_span[i];
            bf -= lim_a[i] * wf[i];
        }
        const int p = j >> 1, s = j & 1;
        #pragma unroll
        for (int i = 0; i < 4; i++) sW1[p * 8 + i * 2 + s] = wf[i];
        sB1[j] = bf;
        #pragma unroll
        for (int k = 0; k < 4; k++) sW2[k * 64 + j] = W2[j * 4 + k];
        if (j < 4) sB2[j] = b2[j];
    }
    __syncthreads();

    const float4* __restrict__ w1v = reinterpret_cast<const float4*>(sW1); // [32][2]
    const float2* __restrict__ b1v = reinterpret_cast<const float2*>(sB1); // [32]
    const float4* __restrict__ w2v = reinterpret_cast<const float4*>(sW2); // [4][16]

    const float bb0 = sB2[0], bb1 = sB2[1], bb2 = sB2[2], bb3 = sB2[3];
    const float bbk[4] = {bb0, bb1, bb2, bb3};
    const float lim_a_k[4] = {0.001f, 0.02f, 0.05f, 0.001f};
    const float span_k[4]  = {0.003f, 0.03f, 0.15f, 0.003f};

    const int tid    = blockIdx.x * blockDim.x + threadIdx.x;
    const int stride = gridDim.x * blockDim.x;

    for (int r = tid; r < rows; r += stride) {
        const float4 xv = x[r];
        const float2 x0 = make_float2(xv.x, xv.x);
        const float2 x1 = make_float2(xv.y, xv.y);
        const float2 x2 = make_float2(xv.z, xv.z);
        const float2 x3 = make_float2(xv.w, xv.w);

        // ---- layer 1: h = relu(x @ W1f + b1f), pairs packed in f32x2 ----
        float2 h[NPAIR];
        #pragma unroll
        for (int p = 0; p < NPAIR; p++) {
            const float4 wa = w1v[2 * p];
            const float4 wb = w1v[2 * p + 1];
            float2 acc = b1v[p];
            acc = ffma2(x0, make_float2(wa.x, wa.y), acc);
            acc = ffma2(x1, make_float2(wa.z, wa.w), acc);
            acc = ffma2(x2, make_float2(wb.x, wb.y), acc);
            acc = ffma2(x3, make_float2(wb.z, wb.w), acc);
            acc.x = fmaxf(acc.x, 0.0f);
            acc.y = fmaxf(acc.y, 0.0f);
            h[p] = acc;
        }

        // ---- layer 2 + sigmoid + output scaling ----
        float4 zout;
        float* zp = &zout.x;
        #pragma unroll
        for (int k = 0; k < 4; k++) {
            // two independent partial chains for ILP
            float2 accA = make_float2(0.0f, 0.0f);
            float2 accB = make_float2(0.0f, 0.0f);
            #pragma unroll
            for (int q = 0; q < 16; q += 2) {
                const float4 wA = w2v[k * 16 + q];
                const float4 wB = w2v[k * 16 + q + 1];
                accA = ffma2(h[2 * q],     make_float2(wA.x, wA.y), accA);
                accA = ffma2(h[2 * q + 1], make_float2(wA.z, wA.w), accA);
                accB = ffma2(h[2 * q + 2], make_float2(wB.x, wB.y), accB);
                accB = ffma2(h[2 * q + 3], make_float2(wB.z, wB.w), accB);
            }
            const float y = (accA.x + accA.y) + (accB.x + accB.y) + bbk[k];
            const float e = __expf(-y);
            const float sg = __fdividef(1.0f, 1.0f + e);
            zp[k] = fmaf(span_k[k], sg, lim_a_k[k]);
        }

        out[r] = zout;
    }
}

extern "C" void kernel_launch(void* const* d_in, const int* in_sizes, int n_in,
                              void* d_out, int out_size) {
    const float* x  = (const float*)d_in[0];
    const float* W1 = (const float*)d_in[1];
    const float* b1 = (const float*)d_in[2];
    const float* W2 = (const float*)d_in[3];
    const float* b2 = (const float*)d_in[4];
    const int rows = in_sizes[0] / 4;

    const int threads = 256;
    const int blocks  = 2048;   // grid-stride: ~8 rows/thread at 4.19M rows
    mlp_kernel<<<blocks, threads>>>(
        (const float4*)x, W1, b1, W2, b2, (float4*)d_out, rows);
}

// round 2
// speedup vs baseline: 3.5206x; 3.5206x over previous
#include <cuda_runtime.h>

// Net_90434831385322: z = LIM_A + span*sigmoid( relu(((x-LIM_A)/span) @ W1 + b1) @ W2 + b2 )
//
// R2 design:
//  - Input scaling folded into W1/b1 (W1f = W1/span, b1f = b1 - lim_a@W1f).
//  - Layer2 fused into layer1 loop: stream over 64 hidden units, never store h[].
//  - f32x2 lanes hold a ROW PAIR; all weights pre-DUPLICATED in shared memory so
//    every ffma2 operand is a natural even-aligned register pair (no MOVs).
//  - 4 rows per thread (2 row-pairs) to amortize the 5 LDS.128 per hidden unit.

union F2U { float2 f; unsigned long long u; };

__device__ __forceinline__ float2 ffma2(float2 a, float2 b, float2 c) {
    F2U A, B, C, D;
    A.f = a; B.f = b; C.f = c;
    asm("fma.rn.f32x2 %0, %1, %2, %3;"
        : "=l"(D.u) : "l"(A.u), "l"(B.u), "l"(C.u));
    return D.f;
}

#define HID 64

// shared pack per hidden unit j (as float4, 5 per j):
//  [0] = (w1f0,w1f0, w1f1,w1f1)   dup'd W1f[0][j], W1f[1][j]
//  [1] = (w1f2,w1f2, w1f3,w1f3)
//  [2] = (w2_0,w2_0, w2_1,w2_1)   dup'd W2[j][0], W2[j][1]
//  [3] = (w2_2,w2_2, w2_3,w2_3)
//  [4] = (b1f ,b1f , 0   ,0   )
__global__ void __launch_bounds__(256, 3)
mlp_kernel(const float4* __restrict__ x,
           const float* __restrict__ W1,   // [4][64]
           const float* __restrict__ b1,   // [64]
           const float* __restrict__ W2,   // [64][4]
           const float* __restrict__ b2,   // [4]
           float4* __restrict__ out,
           int rows)
{
    __shared__ float4 sW[HID * 5];

    const int t = threadIdx.x;
    if (t < HID) {
        const float lim_a[4]    = {0.001f, 0.02f, 0.05f, 0.001f};
        const float inv_span[4] = {1.0f/0.003f, 1.0f/0.03f, 1.0f/0.15f, 1.0f/0.003f};
        const int j = t;
        float w[4];
        float bf = b1[j];
        #pragma unroll
        for (int i = 0; i < 4; i++) {
            w[i] = W1[i * HID + j] * inv_span[i];
            bf -= lim_a[i] * w[i];
        }
        float v2[4];
        #pragma unroll
        for (int k = 0; k < 4; k++) v2[k] = W2[j * 4 + k];

        sW[j * 5 + 0] = make_float4(w[0], w[0], w[1], w[1]);
        sW[j * 5 + 1] = make_float4(w[2], w[2], w[3], w[3]);
        sW[j * 5 + 2] = make_float4(v2[0], v2[0], v2[1], v2[1]);
        sW[j * 5 + 3] = make_float4(v2[2], v2[2], v2[3], v2[3]);
        sW[j * 5 + 4] = make_float4(bf, bf, 0.0f, 0.0f);
    }
    __syncthreads();

    // uniform scalar loads (read-only, broadcast through L1/const path)
    const float bb0 = b2[0], bb1 = b2[1], bb2 = b2[2], bb3 = b2[3];

    const float lim_a_k[4] = {0.001f, 0.02f, 0.05f, 0.001f};
    const float span_k[4]  = {0.003f, 0.03f, 0.15f, 0.003f};

    const int tid     = blockIdx.x * blockDim.x + threadIdx.x;
    const int gstride = gridDim.x * blockDim.x * 4;

    for (int r = tid * 4; r < rows; r += gstride) {
        // ---- load 4 rows (clamped for tail safety) ----
        float4 xr[4];
        #pragma unroll
        for (int i = 0; i < 4; i++) {
            int ri = r + i;
            xr[i] = x[ri < rows ? ri : (rows - 1)];
        }

        // pack row-pairs: xp[pr][i] = (x_i(row 2pr), x_i(row 2pr+1))
        float2 xp[2][4];
        #pragma unroll
        for (int pr = 0; pr < 2; pr++) {
            xp[pr][0] = make_float2(xr[2*pr].x, xr[2*pr+1].x);
            xp[pr][1] = make_float2(xr[2*pr].y, xr[2*pr+1].y);
            xp[pr][2] = make_float2(xr[2*pr].z, xr[2*pr+1].z);
            xp[pr][3] = make_float2(xr[2*pr].w, xr[2*pr+1].w);
        }

        // output accumulators: y[pr][k] = (y_k(row0), y_k(row1)), init bias
        float2 y[2][4];
        #pragma unroll
        for (int pr = 0; pr < 2; pr++) {
            y[pr][0] = make_float2(bb0, bb0);
            y[pr][1] = make_float2(bb1, bb1);
            y[pr][2] = make_float2(bb2, bb2);
            y[pr][3] = make_float2(bb3, bb3);
        }

        // ---- fused layer1+relu+layer2 over 64 hidden units ----
        #pragma unroll 16
        for (int j = 0; j < HID; j++) {
            const float4 wA = sW[j * 5 + 0];
            const float4 wB = sW[j * 5 + 1];
            const float4 wC = sW[j * 5 + 2];
            const float4 wD = sW[j * 5 + 3];
            const float4 wE = sW[j * 5 + 4];

            #pragma unroll
            for (int pr = 0; pr < 2; pr++) {
                float2 h = make_float2(wE.x, wE.y);
                h = ffma2(xp[pr][0], make_float2(wA.x, wA.y), h);
                h = ffma2(xp[pr][1], make_float2(wA.z, wA.w), h);
                h = ffma2(xp[pr][2], make_float2(wB.x, wB.y), h);
                h = ffma2(xp[pr][3], make_float2(wB.z, wB.w), h);
                h.x = fmaxf(h.x, 0.0f);   // FMNMX -> alu pipe
                h.y = fmaxf(h.y, 0.0f);
                y[pr][0] = ffma2(h, make_float2(wC.x, wC.y), y[pr][0]);
                y[pr][1] = ffma2(h, make_float2(wC.z, wC.w), y[pr][1]);
                y[pr][2] = ffma2(h, make_float2(wD.x, wD.y), y[pr][2]);
                y[pr][3] = ffma2(h, make_float2(wD.z, wD.w), y[pr][3]);
            }
        }

        // ---- sigmoid epilogue + store ----
        #pragma unroll
        for (int pr = 0; pr < 2; pr++) {
            float4 o0, o1;
            float* p0 = &o0.x;
            float* p1 = &o1.x;
            #pragma unroll
            for (int k = 0; k < 4; k++) {
                float s0 = __fdividef(1.0f, 1.0f + __expf(-y[pr][k].x));
                float s1 = __fdividef(1.0f, 1.0f + __expf(-y[pr][k].y));
                p0[k] = fmaf(span_k[k], s0, lim_a_k[k]);
                p1[k] = fmaf(span_k[k], s1, lim_a_k[k]);
            }
            int r0 = r + 2 * pr;
            if (r0 < rows)     out[r0]     = o0;
            if (r0 + 1 < rows) out[r0 + 1] = o1;
        }
    }
}

extern "C" void kernel_launch(void* const* d_in, const int* in_sizes, int n_in,
                              void* d_out, int out_size) {
    const float* x  = (const float*)d_in[0];
    const float* W1 = (const float*)d_in[1];
    const float* b1 = (const float*)d_in[2];
    const float* W2 = (const float*)d_in[3];
    const float* b2 = (const float*)d_in[4];
    const int rows = in_sizes[0] / 4;

    const int threads = 256;
    // 4 rows/thread: 4096 blocks * 256 threads * 4 rows = 4,194,304 (exact cover)
    const int blocks = (rows + threads * 4 - 1) / (threads * 4);
    mlp_kernel<<<blocks, threads>>>(
        (const float4*)x, W1, b1, W2, b2, (float4*)d_out, rows);
}